// round 4
// baseline (speedup 1.0000x reference)
#include <cuda_runtime.h>
#include <math.h>

// Problem constants
#define BB  8
#define SS  1024
#define EE  512
#define HH  8
#define DD  64
#define LL  6
#define HFF 2048
#define MM  (BB*SS)          // 8192 rows
#define INF_MASK 1000000.0f

// ---------------------------------------------------------------------------
// Scratch (device globals: allocation inside kernel_launch is forbidden)
// ---------------------------------------------------------------------------
__device__ float g_x  [MM*EE];
__device__ float g_q  [MM*EE];
__device__ float g_k  [MM*EE];
__device__ float g_v  [MM*EE];
__device__ float g_att[MM*EE];
__device__ float g_tmp[MM*EE];
__device__ float g_h  [MM*HFF];
__device__ float g_bias[BB*SS];
__device__ int   g_maskmode;

// ---------------------------------------------------------------------------
// Mask handling: detect 1-byte vs 4-byte mask encoding, build additive bias.
// In a 4-byte {0,1} encoding (int32 or float32 1.0f), every byte at index
// i%4==1 is zero. A bool/int8 mask with ~half true hits a nonzero there with
// overwhelming probability over 4096 bytes.
// ---------------------------------------------------------------------------
__global__ void detect_mask_kernel(const unsigned char* __restrict__ m)
{
    __shared__ int found;
    if (threadIdx.x == 0) found = 0;
    __syncthreads();
    int f = 0;
    for (int i = threadIdx.x; i < 4096; i += 256)
        if ((i & 3) == 1 && m[i]) f = 1;
    if (f) atomicExch(&found, 1);
    __syncthreads();
    if (threadIdx.x == 0) g_maskmode = found;   // 1 => byte mask, 0 => 4-byte mask
}

__global__ void mask_bias_kernel(const void* __restrict__ mask, float* __restrict__ bias)
{
    int i = blockIdx.x * 256 + threadIdx.x;
    if (i >= BB * SS) return;
    int v;
    if (g_maskmode)
        v = ((const unsigned char*)mask)[i] != 0;
    else
        v = ((const unsigned int*)mask)[i] != 0;   // covers int32 and float32 1.0f
    bias[i] = v ? 0.0f : INF_MASK;
}

// ---------------------------------------------------------------------------
// GELU (tanh approximation, matches reference)
// ---------------------------------------------------------------------------
__device__ __forceinline__ float gelu_f(float x)
{
    const float c = 0.7978845608028654f;    // sqrt(2/pi)
    float t = tanhf(c * (x + 0.044715f * x * x * x));
    return 0.5f * x * (1.0f + t);
}

// ---------------------------------------------------------------------------
// SGEMM: out[M,N] = A[M,K] * W[N,K]^T + bias[N]   (optional GELU epilogue)
// Block 128x128, K-tile 16, 256 threads, 8x8 register tile per thread.
// ---------------------------------------------------------------------------
#define TM 128
#define TN 128
#define TK 16

__device__ __forceinline__ void gemm_body(
    const float* __restrict__ A, const float* __restrict__ W,
    const float* __restrict__ bias, float* __restrict__ out,
    int N, int K, int m0, int n0, bool do_gelu)
{
    __shared__ float As[TK][TM + 4];
    __shared__ float Ws[TK][TN + 4];

    const int tid = threadIdx.x;         // 0..255
    const int tx  = tid & 15;
    const int ty  = tid >> 4;
    const int lk  = (tid & 3) * 4;       // k offset within tile: 0,4,8,12
    const int lr  = tid >> 2;            // row 0..63

    float acc[8][8];
#pragma unroll
    for (int i = 0; i < 8; i++)
#pragma unroll
        for (int j = 0; j < 8; j++) acc[i][j] = 0.0f;

    for (int k0 = 0; k0 < K; k0 += TK) {
#pragma unroll
        for (int h = 0; h < 2; ++h) {
            int r = lr + h * 64;
            float4 av = *(const float4*)(A + (size_t)(m0 + r) * K + k0 + lk);
            As[lk + 0][r] = av.x; As[lk + 1][r] = av.y;
            As[lk + 2][r] = av.z; As[lk + 3][r] = av.w;
            float4 wv = *(const float4*)(W + (size_t)(n0 + r) * K + k0 + lk);
            Ws[lk + 0][r] = wv.x; Ws[lk + 1][r] = wv.y;
            Ws[lk + 2][r] = wv.z; Ws[lk + 3][r] = wv.w;
        }
        __syncthreads();
#pragma unroll
        for (int kk = 0; kk < TK; ++kk) {
            float a[8], w[8];
            *(float4*)&a[0] = *(const float4*)&As[kk][ty * 8];
            *(float4*)&a[4] = *(const float4*)&As[kk][ty * 8 + 4];
            *(float4*)&w[0] = *(const float4*)&Ws[kk][tx * 8];
            *(float4*)&w[4] = *(const float4*)&Ws[kk][tx * 8 + 4];
#pragma unroll
            for (int i = 0; i < 8; i++)
#pragma unroll
                for (int j = 0; j < 8; j++)
                    acc[i][j] = fmaf(a[i], w[j], acc[i][j]);
        }
        __syncthreads();
    }

#pragma unroll
    for (int i = 0; i < 8; i++) {
        int m = m0 + ty * 8 + i;
#pragma unroll
        for (int j = 0; j < 8; j += 4) {
            int n = n0 + tx * 8 + j;
            float4 v;
            v.x = acc[i][j + 0] + bias[n + 0];
            v.y = acc[i][j + 1] + bias[n + 1];
            v.z = acc[i][j + 2] + bias[n + 2];
            v.w = acc[i][j + 3] + bias[n + 3];
            if (do_gelu) {
                v.x = gelu_f(v.x); v.y = gelu_f(v.y);
                v.z = gelu_f(v.z); v.w = gelu_f(v.w);
            }
            *(float4*)(out + (size_t)m * N + n) = v;
        }
    }
}

__global__ __launch_bounds__(256)
void gemm_kernel(const float* __restrict__ A, const float* __restrict__ W,
                 const float* __restrict__ bias, float* __restrict__ out,
                 int N, int K, int do_gelu)
{
    gemm_body(A, W, bias, out, N, K, blockIdx.y * TM, blockIdx.x * TN, do_gelu != 0);
}

// Fused Q/K/V projection: blockIdx.z selects which of the three GEMMs.
__global__ __launch_bounds__(256)
void qkv_kernel(const float* __restrict__ A,
                const float* __restrict__ WQ, const float* __restrict__ bQ, float* __restrict__ Q,
                const float* __restrict__ WK, const float* __restrict__ bK, float* __restrict__ Kp,
                const float* __restrict__ WV, const float* __restrict__ bV, float* __restrict__ Vp)
{
    const float* W; const float* b; float* o;
    if (blockIdx.z == 0)      { W = WQ; b = bQ; o = Q;  }
    else if (blockIdx.z == 1) { W = WK; b = bK; o = Kp; }
    else                      { W = WV; b = bV; o = Vp; }
    gemm_body(A, W, b, o, EE, EE, blockIdx.y * TM, blockIdx.x * TN, false);
}

// ---------------------------------------------------------------------------
// Flash attention: one block = one (b, h, 64-row Q tile). Online softmax.
// Dyn smem: Qs[64][68], KVs[64][68], Ps[64][68]  (52224 B)
// ---------------------------------------------------------------------------
#define AP 68
#define ATT_SMEM (3 * 64 * AP * 4)

__global__ __launch_bounds__(256)
void attn_kernel(const float* __restrict__ q, const float* __restrict__ k,
                 const float* __restrict__ v, const float* __restrict__ bias,
                 float* __restrict__ out)
{
    extern __shared__ float sm[];
    float* Qs  = sm;
    float* KVs = sm + 64 * AP;
    float* Ps  = sm + 2 * 64 * AP;

    const int b  = blockIdx.z;
    const int h  = blockIdx.y;
    const int q0 = blockIdx.x * 64;
    const int tid = threadIdx.x;
    const int tx = tid & 15;
    const int ty = tid >> 4;

    const int lc = (tid & 15) * 4;     // d-offset for tile loads
    const int lr = tid >> 4;           // base row for tile loads

    // Load Q tile
#pragma unroll
    for (int i = 0; i < 4; i++) {
        int row = lr + i * 16;
        *(float4*)&Qs[row * AP + lc] =
            *(const float4*)(q + ((size_t)b * SS + q0 + row) * EE + h * DD + lc);
    }

    float m_r[4], l_r[4], acc[4][4];
#pragma unroll
    for (int i = 0; i < 4; i++) {
        m_r[i] = -INFINITY; l_r[i] = 0.0f;
#pragma unroll
        for (int j = 0; j < 4; j++) acc[i][j] = 0.0f;
    }
    const float* bias_b = bias + b * SS;

    for (int t0 = 0; t0 < SS; t0 += 64) {
        __syncthreads();   // previous iteration done with KVs/Ps (also covers Q load)
        // Load K tile
#pragma unroll
        for (int i = 0; i < 4; i++) {
            int row = lr + i * 16;
            *(float4*)&KVs[row * AP + lc] =
                *(const float4*)(k + ((size_t)b * SS + t0 + row) * EE + h * DD + lc);
        }
        __syncthreads();

        // S = Q K^T  (scaled, masked)
        float s[4][4];
#pragma unroll
        for (int i = 0; i < 4; i++)
#pragma unroll
            for (int j = 0; j < 4; j++) s[i][j] = 0.0f;

        for (int d = 0; d < 64; d += 4) {
            float4 a[4], bb[4];
#pragma unroll
            for (int i = 0; i < 4; i++) a[i]  = *(const float4*)&Qs[(ty * 4 + i) * AP + d];
#pragma unroll
            for (int j = 0; j < 4; j++) bb[j] = *(const float4*)&KVs[(tx * 4 + j) * AP + d];
#pragma unroll
            for (int i = 0; i < 4; i++)
#pragma unroll
                for (int j = 0; j < 4; j++) {
                    s[i][j] = fmaf(a[i].x, bb[j].x, s[i][j]);
                    s[i][j] = fmaf(a[i].y, bb[j].y, s[i][j]);
                    s[i][j] = fmaf(a[i].z, bb[j].z, s[i][j]);
                    s[i][j] = fmaf(a[i].w, bb[j].w, s[i][j]);
                }
        }
        float bv[4];
#pragma unroll
        for (int j = 0; j < 4; j++) bv[j] = bias_b[t0 + tx * 4 + j];
#pragma unroll
        for (int i = 0; i < 4; i++)
#pragma unroll
            for (int j = 0; j < 4; j++)
                s[i][j] = s[i][j] * 0.125f - bv[j];

        // Online softmax (row reductions over 16 tx lanes of the half-warp)
#pragma unroll
        for (int i = 0; i < 4; i++) {
            float tmax = fmaxf(fmaxf(s[i][0], s[i][1]), fmaxf(s[i][2], s[i][3]));
#pragma unroll
            for (int o = 8; o; o >>= 1)
                tmax = fmaxf(tmax, __shfl_xor_sync(0xffffffffu, tmax, o));
            float mn = fmaxf(m_r[i], tmax);
            float p[4], rs = 0.0f;
#pragma unroll
            for (int j = 0; j < 4; j++) { p[j] = __expf(s[i][j] - mn); rs += p[j]; }
#pragma unroll
            for (int o = 8; o; o >>= 1)
                rs += __shfl_xor_sync(0xffffffffu, rs, o);
            float alpha = __expf(m_r[i] - mn);
            l_r[i] = l_r[i] * alpha + rs;
            m_r[i] = mn;
#pragma unroll
            for (int jd = 0; jd < 4; jd++) acc[i][jd] *= alpha;
#pragma unroll
            for (int j = 0; j < 4; j++) Ps[(ty * 4 + i) * AP + tx * 4 + j] = p[j];
        }
        __syncthreads();   // Ps written, K reads done

        // Load V tile (reuse KVs)
#pragma unroll
        for (int i = 0; i < 4; i++) {
            int row = lr + i * 16;
            *(float4*)&KVs[row * AP + lc] =
                *(const float4*)(v + ((size_t)b * SS + t0 + row) * EE + h * DD + lc);
        }
        __syncthreads();

        // acc += P * V
        for (int t = 0; t < 64; t++) {
            float pr[4];
#pragma unroll
            for (int i = 0; i < 4; i++) pr[i] = Ps[(ty * 4 + i) * AP + t];
            float4 vv = *(const float4*)&KVs[t * AP + tx * 4];
#pragma unroll
            for (int i = 0; i < 4; i++) {
                acc[i][0] = fmaf(pr[i], vv.x, acc[i][0]);
                acc[i][1] = fmaf(pr[i], vv.y, acc[i][1]);
                acc[i][2] = fmaf(pr[i], vv.z, acc[i][2]);
                acc[i][3] = fmaf(pr[i], vv.w, acc[i][3]);
            }
        }
    }

    // Write O
#pragma unroll
    for (int i = 0; i < 4; i++) {
        float inv = 1.0f / l_r[i];
        float4 o4;
        o4.x = acc[i][0] * inv; o4.y = acc[i][1] * inv;
        o4.z = acc[i][2] * inv; o4.w = acc[i][3] * inv;
        *(float4*)(out + ((size_t)b * SS + q0 + ty * 4 + i) * EE + h * DD + tx * 4) = o4;
    }
}

// ---------------------------------------------------------------------------
// Residual add + LayerNorm: one block per row (E = 512, 256 threads x 2 elems)
// ---------------------------------------------------------------------------
__global__ __launch_bounds__(256)
void add_ln_kernel(const float* __restrict__ x, const float* __restrict__ r,
                   const float* __restrict__ g, const float* __restrict__ bt,
                   float* __restrict__ out)
{
    const int row = blockIdx.x;
    const int t = threadIdx.x;
    const size_t base = (size_t)row * EE;

    float v0 = x[base + t]       + r[base + t];
    float v1 = x[base + t + 256] + r[base + t + 256];
    float s  = v0 + v1;
    float ss = v0 * v0 + v1 * v1;
#pragma unroll
    for (int o = 16; o; o >>= 1) {
        s  += __shfl_xor_sync(0xffffffffu, s, o);
        ss += __shfl_xor_sync(0xffffffffu, ss, o);
    }
    __shared__ float sh_s[8], sh_ss[8];
    if ((t & 31) == 0) { sh_s[t >> 5] = s; sh_ss[t >> 5] = ss; }
    __syncthreads();
    float tot = 0.0f, tot2 = 0.0f;
#pragma unroll
    for (int i = 0; i < 8; i++) { tot += sh_s[i]; tot2 += sh_ss[i]; }
    float mean = tot * (1.0f / EE);
    float var  = tot2 * (1.0f / EE) - mean * mean;
    float inv  = rsqrtf(var + 1e-5f);

    out[base + t]       = g[t]       * ((v0 - mean) * inv) + bt[t];
    out[base + t + 256] = g[t + 256] * ((v1 - mean) * inv) + bt[t + 256];
}

// ---------------------------------------------------------------------------
// Host driver
// ---------------------------------------------------------------------------
extern "C" void kernel_launch(void* const* d_in, const int* in_sizes, int n_in,
                              void* d_out, int out_size)
{
    (void)in_sizes; (void)n_in; (void)out_size;

    const float* x_in = (const float*)d_in[0];
    const void*  mask = d_in[1];
    const float* WQ = (const float*)d_in[2];
    const float* bQ = (const float*)d_in[3];
    const float* WK = (const float*)d_in[4];
    const float* bK = (const float*)d_in[5];
    const float* WV = (const float*)d_in[6];
    const float* bV = (const float*)d_in[7];
    const float* WO = (const float*)d_in[8];
    const float* bO = (const float*)d_in[9];
    const float* W1 = (const float*)d_in[10];
    const float* b1 = (const float*)d_in[11];
    const float* W2 = (const float*)d_in[12];
    const float* b2 = (const float*)d_in[13];
    const float* g1 = (const float*)d_in[14];
    const float* t1 = (const float*)d_in[15];
    const float* g2 = (const float*)d_in[16];
    const float* t2 = (const float*)d_in[17];

    float *px, *pq, *pk, *pv, *patt, *ptmp, *ph, *pbias;
    cudaGetSymbolAddress((void**)&px,   g_x);
    cudaGetSymbolAddress((void**)&pq,   g_q);
    cudaGetSymbolAddress((void**)&pk,   g_k);
    cudaGetSymbolAddress((void**)&pv,   g_v);
    cudaGetSymbolAddress((void**)&patt, g_att);
    cudaGetSymbolAddress((void**)&ptmp, g_tmp);
    cudaGetSymbolAddress((void**)&ph,   g_h);
    cudaGetSymbolAddress((void**)&pbias, g_bias);

    cudaMemcpyAsync(px, x_in, sizeof(float) * MM * EE, cudaMemcpyDeviceToDevice);
    detect_mask_kernel<<<1, 256>>>((const unsigned char*)mask);
    mask_bias_kernel<<<(BB * SS + 255) / 256, 256>>>(mask, pbias);

    cudaFuncSetAttribute(attn_kernel, cudaFuncAttributeMaxDynamicSharedMemorySize, ATT_SMEM);

    for (int l = 0; l < LL; l++) {
        const float* wq = WQ + (size_t)l * EE * EE;
        const float* wk = WK + (size_t)l * EE * EE;
        const float* wv = WV + (size_t)l * EE * EE;
        const float* wo = WO + (size_t)l * EE * EE;
        const float* w1 = W1 + (size_t)l * HFF * EE;
        const float* w2 = W2 + (size_t)l * EE * HFF;

        qkv_kernel<<<dim3(EE / TN, MM / TM, 3), 256>>>(
            px, wq, bQ + l * EE, pq, wk, bK + l * EE, pk, wv, bV + l * EE, pv);

        attn_kernel<<<dim3(SS / 64, HH, BB), 256, ATT_SMEM>>>(pq, pk, pv, pbias, patt);

        gemm_kernel<<<dim3(EE / TN, MM / TM), 256>>>(patt, wo, bO + l * EE, ptmp, EE, EE, 0);

        add_ln_kernel<<<MM, 256>>>(px, ptmp, g1 + l * EE, t1 + l * EE, px);

        gemm_kernel<<<dim3(HFF / TN, MM / TM), 256>>>(px, w1, b1 + l * HFF, ph, HFF, EE, 1);

        gemm_kernel<<<dim3(EE / TN, MM / TM), 256>>>(ph, w2, b2 + l * EE, ptmp, EE, HFF, 0);

        float* xout = (l == LL - 1) ? (float*)d_out : px;
        add_ln_kernel<<<MM, 256>>>(px, ptmp, g2 + l * EE, t2 + l * EE, xout);
    }
}

// round 7
// speedup vs baseline: 1.4477x; 1.4477x over previous
#include <cuda_runtime.h>
#include <cuda_bf16.h>
#include <math.h>
#include <stdint.h>

// Problem constants
#define BB  8
#define SS  1024
#define EE  512
#define HH  8
#define DD  64
#define LL  6
#define HFF 2048
#define MM  (BB*SS)          // 8192 rows
#define INF_MASK 1000000.0f

// ---------------------------------------------------------------------------
// Scratch (device globals: allocation inside kernel_launch is forbidden)
// ---------------------------------------------------------------------------
__device__ float g_x  [MM*EE];
__device__ float g_q  [MM*EE];
__device__ float g_k  [MM*EE];
__device__ float g_v  [MM*EE];
__device__ float g_att[MM*EE];
__device__ float g_tmp[MM*EE];
__device__ float g_h  [MM*HFF];
__device__ float g_bias[BB*SS];
__device__ int   g_maskmode;

// ---------------------------------------------------------------------------
// Mask handling (unchanged)
// ---------------------------------------------------------------------------
__global__ void detect_mask_kernel(const unsigned char* __restrict__ m)
{
    __shared__ int found;
    if (threadIdx.x == 0) found = 0;
    __syncthreads();
    int f = 0;
    for (int i = threadIdx.x; i < 4096; i += 256)
        if ((i & 3) == 1 && m[i]) f = 1;
    if (f) atomicExch(&found, 1);
    __syncthreads();
    if (threadIdx.x == 0) g_maskmode = found;
}

__global__ void mask_bias_kernel(const void* __restrict__ mask, float* __restrict__ bias)
{
    int i = blockIdx.x * 256 + threadIdx.x;
    if (i >= BB * SS) return;
    int v;
    if (g_maskmode)
        v = ((const unsigned char*)mask)[i] != 0;
    else
        v = ((const unsigned int*)mask)[i] != 0;
    bias[i] = v ? 0.0f : INF_MASK;
}

// ---------------------------------------------------------------------------
// GELU (tanh approximation, matches reference)
// ---------------------------------------------------------------------------
__device__ __forceinline__ float gelu_f(float x)
{
    const float c = 0.7978845608028654f;
    float t = tanhf(c * (x + 0.044715f * x * x * x));
    return 0.5f * x * (1.0f + t);
}

// ---------------------------------------------------------------------------
// mma.sync helpers (base sm_103-legal; no tcgen05)
// ---------------------------------------------------------------------------
__device__ __forceinline__ uint32_t smem_u32(const void* p)
{
    uint32_t a;
    asm("{ .reg .u64 t; cvta.to.shared.u64 t, %1; cvt.u32.u64 %0, t; }"
        : "=r"(a) : "l"(p));
    return a;
}

__device__ __forceinline__ void ldm_x4(uint32_t* r, uint32_t addr)
{
    asm volatile("ldmatrix.sync.aligned.m8n8.x4.shared.b16 {%0,%1,%2,%3}, [%4];"
                 : "=r"(r[0]), "=r"(r[1]), "=r"(r[2]), "=r"(r[3]) : "r"(addr));
}

__device__ __forceinline__ void mma_bf16(float* d,
                                         const uint32_t* a, uint32_t b0, uint32_t b1)
{
    asm volatile(
        "mma.sync.aligned.m16n8k16.row.col.f32.bf16.bf16.f32 "
        "{%0,%1,%2,%3}, {%4,%5,%6,%7}, {%8,%9}, {%0,%1,%2,%3};"
        : "+f"(d[0]), "+f"(d[1]), "+f"(d[2]), "+f"(d[3])
        : "r"(a[0]), "r"(a[1]), "r"(a[2]), "r"(a[3]), "r"(b0), "r"(b1));
}

// split float -> bf16 hi + bf16 lo, packed pairs for SMEM
__device__ __forceinline__ void split2(float x, float y, uint32_t& hi, uint32_t& lo)
{
    __nv_bfloat16 hx = __float2bfloat16(x);
    __nv_bfloat16 hy = __float2bfloat16(y);
    __nv_bfloat16 lx = __float2bfloat16(x - __bfloat162float(hx));
    __nv_bfloat16 ly = __float2bfloat16(y - __bfloat162float(hy));
    __nv_bfloat162 h2 = __halves2bfloat162(hx, hy);
    __nv_bfloat162 l2 = __halves2bfloat162(lx, ly);
    hi = *(uint32_t*)&h2;
    lo = *(uint32_t*)&l2;
}

// ---------------------------------------------------------------------------
// bf16x3 HMMA GEMM:  out[M,N] = A[M,K] * W[N,K]^T + bias[N]  (+ optional GELU)
// CTA tile 128x128, K-tile 32. 8 warps, warp tile 32(M) x 64(N).
// SMEM: Ah/Al/Bh/Bl each 128 rows x 32 bf16, row stride 80B (conflict-free
// for ldmatrix: 5*16B stride, 5 coprime 8).
// ---------------------------------------------------------------------------
#define GST 80                 // row stride bytes
#define SA_H 0
#define SA_L 10240
#define SB_H 20480
#define SB_L 30720
#define GEMM_SMEM_BYTES 40960

__device__ __forceinline__ void hgemm_cta(
    const float* __restrict__ A, const float* __restrict__ W,
    const float* __restrict__ bias, float* __restrict__ out,
    int N, int K, int m0, int n0, bool do_gelu, char* sm)
{
    const uint32_t smb = smem_u32(sm);
    const int tid  = threadIdx.x;
    const int lane = tid & 31;
    const int wid  = tid >> 5;
    const int wm   = wid & 3;        // M warp group (0..3) -> rows wm*32
    const int wn   = wid >> 2;       // N warp group (0..1) -> cols wn*64

    // global load mapping: 128 rows x 32 cols per tile, fp32
    const int lrow  = tid >> 1;          // 0..127
    const int cbase = (tid & 1) * 16;    // 0 or 16

    const float* gA = A + (size_t)(m0 + lrow) * K + cbase;
    const float* gB = W + (size_t)(n0 + lrow) * K + cbase;
    const uint32_t srowA = (uint32_t)lrow * GST + (uint32_t)cbase * 2;

    // ldmatrix lane addressing
    const int lro = (lane & 7) + ((lane >> 3) & 1) * 8;   // row offset 0..15
    const int lck = (lane >> 4) * 16;                      // k-chunk byte 0/16
    const uint32_t aAddr = smb + (uint32_t)(wm * 32 + lro) * GST + lck;
    const uint32_t bAddr = smb + SB_H + (uint32_t)(wn * 64 + lro) * GST + lck;

    float acc[2][8][4];
#pragma unroll
    for (int i = 0; i < 2; i++)
#pragma unroll
        for (int j = 0; j < 8; j++)
#pragma unroll
            for (int c = 0; c < 4; c++) acc[i][j][c] = 0.0f;

    const int KT = K >> 5;
    for (int kt = 0; kt < KT; ++kt) {
        // ---- fill SMEM (convert fp32 -> bf16 hi/lo) ----
#pragma unroll
        for (int i = 0; i < 4; ++i) {
            float4 a = *(const float4*)(gA + kt * 32 + i * 4);
            uint32_t h0, l0, h1, l1;
            split2(a.x, a.y, h0, l0);
            split2(a.z, a.w, h1, l1);
            uint32_t off = srowA + i * 8;
            *(uint2*)(sm + SA_H + off) = make_uint2(h0, h1);
            *(uint2*)(sm + SA_L + off) = make_uint2(l0, l1);

            float4 b = *(const float4*)(gB + kt * 32 + i * 4);
            split2(b.x, b.y, h0, l0);
            split2(b.z, b.w, h1, l1);
            *(uint2*)(sm + SB_H + off) = make_uint2(h0, h1);
            *(uint2*)(sm + SB_L + off) = make_uint2(l0, l1);
        }
        __syncthreads();

        // ---- compute: 2 k16 steps ----
#pragma unroll
        for (int ks = 0; ks < 2; ++ks) {
            const uint32_t kb = ks * 32;
            uint32_t ah[2][4], al[2][4];
#pragma unroll
            for (int mi = 0; mi < 2; ++mi) {
                ldm_x4(ah[mi], aAddr + SA_H + mi * (16 * GST) + kb);
                ldm_x4(al[mi], aAddr + SA_L + mi * (16 * GST) + kb);
            }
#pragma unroll
            for (int ng = 0; ng < 4; ++ng) {        // 16 N-cols per group
                uint32_t bh[4], bl[4];
                ldm_x4(bh, bAddr + ng * (16 * GST) + kb);
                ldm_x4(bl, bAddr + (SB_L - SB_H) + ng * (16 * GST) + kb);
#pragma unroll
                for (int mi = 0; mi < 2; ++mi) {
#pragma unroll
                    for (int hf = 0; hf < 2; ++hf) {
                        float* d = acc[mi][ng * 2 + hf];
                        mma_bf16(d, ah[mi], bh[hf], bh[2 + hf]);
                        mma_bf16(d, al[mi], bh[hf], bh[2 + hf]);
                        mma_bf16(d, ah[mi], bl[hf], bl[2 + hf]);
                    }
                }
            }
        }
        __syncthreads();
    }

    // ---- epilogue: bias (+gelu), direct global store ----
    const int r0 = m0 + wm * 32 + (lane >> 2);
    const int c0 = n0 + wn * 64 + (lane & 3) * 2;
#pragma unroll
    for (int mi = 0; mi < 2; ++mi) {
#pragma unroll
        for (int nf = 0; nf < 8; ++nf) {
            int col = c0 + nf * 8;
            float b0 = bias[col], b1 = bias[col + 1];
#pragma unroll
            for (int half = 0; half < 2; ++half) {
                int row = r0 + mi * 16 + half * 8;
                float v0 = acc[mi][nf][half * 2 + 0] + b0;
                float v1 = acc[mi][nf][half * 2 + 1] + b1;
                if (do_gelu) { v0 = gelu_f(v0); v1 = gelu_f(v1); }
                *(float2*)(out + (size_t)row * N + col) = make_float2(v0, v1);
            }
        }
    }
}

__global__ __launch_bounds__(256)
void hgemm_kernel(const float* __restrict__ A, const float* __restrict__ W,
                  const float* __restrict__ bias, float* __restrict__ out,
                  int N, int K, int do_gelu)
{
    __shared__ char sm[GEMM_SMEM_BYTES];
    hgemm_cta(A, W, bias, out, N, K, blockIdx.y * 128, blockIdx.x * 128,
              do_gelu != 0, sm);
}

__global__ __launch_bounds__(256)
void qkv_hgemm_kernel(const float* __restrict__ A,
                      const float* __restrict__ WQ, const float* __restrict__ bQ, float* __restrict__ Q,
                      const float* __restrict__ WK, const float* __restrict__ bK, float* __restrict__ Kp,
                      const float* __restrict__ WV, const float* __restrict__ bV, float* __restrict__ Vp)
{
    __shared__ char sm[GEMM_SMEM_BYTES];
    const float* W; const float* b; float* o;
    if (blockIdx.z == 0)      { W = WQ; b = bQ; o = Q;  }
    else if (blockIdx.z == 1) { W = WK; b = bK; o = Kp; }
    else                      { W = WV; b = bV; o = Vp; }
    hgemm_cta(A, W, b, o, EE, EE, blockIdx.y * 128, blockIdx.x * 128, false, sm);
}

// ---------------------------------------------------------------------------
// Flash attention (unchanged from R3 — passed at rel_err 5.7e-7)
// ---------------------------------------------------------------------------
#define AP 68
#define ATT_SMEM (3 * 64 * AP * 4)

__global__ __launch_bounds__(256)
void attn_kernel(const float* __restrict__ q, const float* __restrict__ k,
                 const float* __restrict__ v, const float* __restrict__ bias,
                 float* __restrict__ out)
{
    extern __shared__ float smf[];
    float* Qs  = smf;
    float* KVs = smf + 64 * AP;
    float* Ps  = smf + 2 * 64 * AP;

    const int b  = blockIdx.z;
    const int h  = blockIdx.y;
    const int q0 = blockIdx.x * 64;
    const int tid = threadIdx.x;
    const int tx = tid & 15;
    const int ty = tid >> 4;

    const int lc = (tid & 15) * 4;
    const int lr = tid >> 4;

#pragma unroll
    for (int i = 0; i < 4; i++) {
        int row = lr + i * 16;
        *(float4*)&Qs[row * AP + lc] =
            *(const float4*)(q + ((size_t)b * SS + q0 + row) * EE + h * DD + lc);
    }

    float m_r[4], l_r[4], acc[4][4];
#pragma unroll
    for (int i = 0; i < 4; i++) {
        m_r[i] = -INFINITY; l_r[i] = 0.0f;
#pragma unroll
        for (int j = 0; j < 4; j++) acc[i][j] = 0.0f;
    }
    const float* bias_b = bias + b * SS;

    for (int t0 = 0; t0 < SS; t0 += 64) {
        __syncthreads();
#pragma unroll
        for (int i = 0; i < 4; i++) {
            int row = lr + i * 16;
            *(float4*)&KVs[row * AP + lc] =
                *(const float4*)(k + ((size_t)b * SS + t0 + row) * EE + h * DD + lc);
        }
        __syncthreads();

        float s[4][4];
#pragma unroll
        for (int i = 0; i < 4; i++)
#pragma unroll
            for (int j = 0; j < 4; j++) s[i][j] = 0.0f;

        for (int d = 0; d < 64; d += 4) {
            float4 a[4], bb[4];
#pragma unroll
            for (int i = 0; i < 4; i++) a[i]  = *(const float4*)&Qs[(ty * 4 + i) * AP + d];
#pragma unroll
            for (int j = 0; j < 4; j++) bb[j] = *(const float4*)&KVs[(tx * 4 + j) * AP + d];
#pragma unroll
            for (int i = 0; i < 4; i++)
#pragma unroll
                for (int j = 0; j < 4; j++) {
                    s[i][j] = fmaf(a[i].x, bb[j].x, s[i][j]);
                    s[i][j] = fmaf(a[i].y, bb[j].y, s[i][j]);
                    s[i][j] = fmaf(a[i].z, bb[j].z, s[i][j]);
                    s[i][j] = fmaf(a[i].w, bb[j].w, s[i][j]);
                }
        }
        float bv[4];
#pragma unroll
        for (int j = 0; j < 4; j++) bv[j] = bias_b[t0 + tx * 4 + j];
#pragma unroll
        for (int i = 0; i < 4; i++)
#pragma unroll
            for (int j = 0; j < 4; j++)
                s[i][j] = s[i][j] * 0.125f - bv[j];

#pragma unroll
        for (int i = 0; i < 4; i++) {
            float tmax = fmaxf(fmaxf(s[i][0], s[i][1]), fmaxf(s[i][2], s[i][3]));
#pragma unroll
            for (int o = 8; o; o >>= 1)
                tmax = fmaxf(tmax, __shfl_xor_sync(0xffffffffu, tmax, o));
            float mn = fmaxf(m_r[i], tmax);
            float p[4], rs = 0.0f;
#pragma unroll
            for (int j = 0; j < 4; j++) { p[j] = __expf(s[i][j] - mn); rs += p[j]; }
#pragma unroll
            for (int o = 8; o; o >>= 1)
                rs += __shfl_xor_sync(0xffffffffu, rs, o);
            float alpha = __expf(m_r[i] - mn);
            l_r[i] = l_r[i] * alpha + rs;
            m_r[i] = mn;
#pragma unroll
            for (int jd = 0; jd < 4; jd++) acc[i][jd] *= alpha;
#pragma unroll
            for (int j = 0; j < 4; j++) Ps[(ty * 4 + i) * AP + tx * 4 + j] = p[j];
        }
        __syncthreads();

#pragma unroll
        for (int i = 0; i < 4; i++) {
            int row = lr + i * 16;
            *(float4*)&KVs[row * AP + lc] =
                *(const float4*)(v + ((size_t)b * SS + t0 + row) * EE + h * DD + lc);
        }
        __syncthreads();

        for (int t = 0; t < 64; t++) {
            float pr[4];
#pragma unroll
            for (int i = 0; i < 4; i++) pr[i] = Ps[(ty * 4 + i) * AP + t];
            float4 vv = *(const float4*)&KVs[t * AP + tx * 4];
#pragma unroll
            for (int i = 0; i < 4; i++) {
                acc[i][0] = fmaf(pr[i], vv.x, acc[i][0]);
                acc[i][1] = fmaf(pr[i], vv.y, acc[i][1]);
                acc[i][2] = fmaf(pr[i], vv.z, acc[i][2]);
                acc[i][3] = fmaf(pr[i], vv.w, acc[i][3]);
            }
        }
    }

#pragma unroll
    for (int i = 0; i < 4; i++) {
        float inv = 1.0f / l_r[i];
        float4 o4;
        o4.x = acc[i][0] * inv; o4.y = acc[i][1] * inv;
        o4.z = acc[i][2] * inv; o4.w = acc[i][3] * inv;
        *(float4*)(out + ((size_t)b * SS + q0 + ty * 4 + i) * EE + h * DD + tx * 4) = o4;
    }
}

// ---------------------------------------------------------------------------
// Residual add + LayerNorm (unchanged)
// ---------------------------------------------------------------------------
__global__ __launch_bounds__(256)
void add_ln_kernel(const float* __restrict__ x, const float* __restrict__ r,
                   const float* __restrict__ g, const float* __restrict__ bt,
                   float* __restrict__ out)
{
    const int row = blockIdx.x;
    const int t = threadIdx.x;
    const size_t base = (size_t)row * EE;

    float v0 = x[base + t]       + r[base + t];
    float v1 = x[base + t + 256] + r[base + t + 256];
    float s  = v0 + v1;
    float ss = v0 * v0 + v1 * v1;
#pragma unroll
    for (int o = 16; o; o >>= 1) {
        s  += __shfl_xor_sync(0xffffffffu, s, o);
        ss += __shfl_xor_sync(0xffffffffu, ss, o);
    }
    __shared__ float sh_s[8], sh_ss[8];
    if ((t & 31) == 0) { sh_s[t >> 5] = s; sh_ss[t >> 5] = ss; }
    __syncthreads();
    float tot = 0.0f, tot2 = 0.0f;
#pragma unroll
    for (int i = 0; i < 8; i++) { tot += sh_s[i]; tot2 += sh_ss[i]; }
    float mean = tot * (1.0f / EE);
    float var  = tot2 * (1.0f / EE) - mean * mean;
    float inv  = rsqrtf(var + 1e-5f);

    out[base + t]       = g[t]       * ((v0 - mean) * inv) + bt[t];
    out[base + t + 256] = g[t + 256] * ((v1 - mean) * inv) + bt[t + 256];
}

// ---------------------------------------------------------------------------
// Host driver
// ---------------------------------------------------------------------------
extern "C" void kernel_launch(void* const* d_in, const int* in_sizes, int n_in,
                              void* d_out, int out_size)
{
    (void)in_sizes; (void)n_in; (void)out_size;

    const float* x_in = (const float*)d_in[0];
    const void*  mask = d_in[1];
    const float* WQ = (const float*)d_in[2];
    const float* bQ = (const float*)d_in[3];
    const float* WK = (const float*)d_in[4];
    const float* bK = (const float*)d_in[5];
    const float* WV = (const float*)d_in[6];
    const float* bV = (const float*)d_in[7];
    const float* WO = (const float*)d_in[8];
    const float* bO = (const float*)d_in[9];
    const float* W1 = (const float*)d_in[10];
    const float* b1 = (const float*)d_in[11];
    const float* W2 = (const float*)d_in[12];
    const float* b2 = (const float*)d_in[13];
    const float* g1 = (const float*)d_in[14];
    const float* t1 = (const float*)d_in[15];
    const float* g2 = (const float*)d_in[16];
    const float* t2 = (const float*)d_in[17];

    float *px, *pq, *pk, *pv, *patt, *ptmp, *ph, *pbias;
    cudaGetSymbolAddress((void**)&px,   g_x);
    cudaGetSymbolAddress((void**)&pq,   g_q);
    cudaGetSymbolAddress((void**)&pk,   g_k);
    cudaGetSymbolAddress((void**)&pv,   g_v);
    cudaGetSymbolAddress((void**)&patt, g_att);
    cudaGetSymbolAddress((void**)&ptmp, g_tmp);
    cudaGetSymbolAddress((void**)&ph,   g_h);
    cudaGetSymbolAddress((void**)&pbias, g_bias);

    cudaMemcpyAsync(px, x_in, sizeof(float) * MM * EE, cudaMemcpyDeviceToDevice);
    detect_mask_kernel<<<1, 256>>>((const unsigned char*)mask);
    mask_bias_kernel<<<(BB * SS + 255) / 256, 256>>>(mask, pbias);

    cudaFuncSetAttribute(attn_kernel, cudaFuncAttributeMaxDynamicSharedMemorySize, ATT_SMEM);

    for (int l = 0; l < LL; l++) {
        const float* wq = WQ + (size_t)l * EE * EE;
        const float* wk = WK + (size_t)l * EE * EE;
        const float* wv = WV + (size_t)l * EE * EE;
        const float* wo = WO + (size_t)l * EE * EE;
        const float* w1 = W1 + (size_t)l * HFF * EE;
        const float* w2 = W2 + (size_t)l * EE * HFF;

        qkv_hgemm_kernel<<<dim3(EE / 128, MM / 128, 3), 256>>>(
            px, wq, bQ + l * EE, pq, wk, bK + l * EE, pk, wv, bV + l * EE, pv);

        attn_kernel<<<dim3(SS / 64, HH, BB), 256, ATT_SMEM>>>(pq, pk, pv, pbias, patt);

        hgemm_kernel<<<dim3(EE / 128, MM / 128), 256>>>(
            patt, wo, bO + l * EE, ptmp, EE, EE, 0);

        add_ln_kernel<<<MM, 256>>>(px, ptmp, g1 + l * EE, t1 + l * EE, px);

        hgemm_kernel<<<dim3(HFF / 128, MM / 128), 256>>>(
            px, w1, b1 + l * HFF, ph, HFF, EE, 1);

        hgemm_kernel<<<dim3(EE / 128, MM / 128), 256>>>(
            ph, w2, b2 + l * EE, ptmp, EE, HFF, 0);

        float* xout = (l == LL - 1) ? (float*)d_out : px;
        add_ln_kernel<<<MM, 256>>>(px, ptmp, g2 + l * EE, t2 + l * EE, xout);
    }
}

// round 8
// speedup vs baseline: 2.7955x; 1.9310x over previous
#include <cuda_runtime.h>
#include <cuda_bf16.h>
#include <math.h>
#include <stdint.h>

// Problem constants
#define BB  8
#define SS  1024
#define EE  512
#define HH  8
#define DD  64
#define LL  6
#define HFF 2048
#define MM  (BB*SS)          // 8192 rows
#define INF_MASK 1000000.0f

// ---------------------------------------------------------------------------
// Scratch (device globals: allocation inside kernel_launch is forbidden)
// ---------------------------------------------------------------------------
__device__ float g_x  [MM*EE];
__device__ float g_q  [MM*EE];
__device__ float g_k  [MM*EE];
__device__ float g_v  [MM*EE];
__device__ float g_att[MM*EE];
__device__ float g_tmp[MM*EE];
__device__ float g_h  [MM*HFF];
__device__ float g_bias[BB*SS];
__device__ int   g_maskmode;

// ---------------------------------------------------------------------------
// Mask handling (unchanged)
// ---------------------------------------------------------------------------
__global__ void detect_mask_kernel(const unsigned char* __restrict__ m)
{
    __shared__ int found;
    if (threadIdx.x == 0) found = 0;
    __syncthreads();
    int f = 0;
    for (int i = threadIdx.x; i < 4096; i += 256)
        if ((i & 3) == 1 && m[i]) f = 1;
    if (f) atomicExch(&found, 1);
    __syncthreads();
    if (threadIdx.x == 0) g_maskmode = found;
}

__global__ void mask_bias_kernel(const void* __restrict__ mask, float* __restrict__ bias)
{
    int i = blockIdx.x * 256 + threadIdx.x;
    if (i >= BB * SS) return;
    int v;
    if (g_maskmode)
        v = ((const unsigned char*)mask)[i] != 0;
    else
        v = ((const unsigned int*)mask)[i] != 0;
    bias[i] = v ? 0.0f : INF_MASK;
}

// ---------------------------------------------------------------------------
// GELU (tanh approximation, matches reference)
// ---------------------------------------------------------------------------
__device__ __forceinline__ float gelu_f(float x)
{
    const float c = 0.7978845608028654f;
    float t = tanhf(c * (x + 0.044715f * x * x * x));
    return 0.5f * x * (1.0f + t);
}

// ---------------------------------------------------------------------------
// mma.sync helpers (base sm_103-legal; no tcgen05)
// ---------------------------------------------------------------------------
__device__ __forceinline__ uint32_t smem_u32(const void* p)
{
    uint32_t a;
    asm("{ .reg .u64 t; cvta.to.shared.u64 t, %1; cvt.u32.u64 %0, t; }"
        : "=r"(a) : "l"(p));
    return a;
}

__device__ __forceinline__ void ldm_x4(uint32_t* r, uint32_t addr)
{
    asm volatile("ldmatrix.sync.aligned.m8n8.x4.shared.b16 {%0,%1,%2,%3}, [%4];"
                 : "=r"(r[0]), "=r"(r[1]), "=r"(r[2]), "=r"(r[3]) : "r"(addr));
}

__device__ __forceinline__ void ldm_x4_trans(uint32_t* r, uint32_t addr)
{
    asm volatile("ldmatrix.sync.aligned.m8n8.x4.trans.shared.b16 {%0,%1,%2,%3}, [%4];"
                 : "=r"(r[0]), "=r"(r[1]), "=r"(r[2]), "=r"(r[3]) : "r"(addr));
}

__device__ __forceinline__ void mma_bf16(float* d,
                                         const uint32_t* a, uint32_t b0, uint32_t b1)
{
    asm volatile(
        "mma.sync.aligned.m16n8k16.row.col.f32.bf16.bf16.f32 "
        "{%0,%1,%2,%3}, {%4,%5,%6,%7}, {%8,%9}, {%0,%1,%2,%3};"
        : "+f"(d[0]), "+f"(d[1]), "+f"(d[2]), "+f"(d[3])
        : "r"(a[0]), "r"(a[1]), "r"(a[2]), "r"(a[3]), "r"(b0), "r"(b1));
}

// split float -> bf16 hi + bf16 lo, packed pairs for SMEM
__device__ __forceinline__ void split2(float x, float y, uint32_t& hi, uint32_t& lo)
{
    __nv_bfloat16 hx = __float2bfloat16(x);
    __nv_bfloat16 hy = __float2bfloat16(y);
    __nv_bfloat16 lx = __float2bfloat16(x - __bfloat162float(hx));
    __nv_bfloat16 ly = __float2bfloat16(y - __bfloat162float(hy));
    __nv_bfloat162 h2 = __halves2bfloat162(hx, hy);
    __nv_bfloat162 l2 = __halves2bfloat162(lx, ly);
    hi = *(uint32_t*)&h2;
    lo = *(uint32_t*)&l2;
}

__device__ __forceinline__ uint32_t pack_bf16(float x, float y)
{
    __nv_bfloat162 h2 = __floats2bfloat162_rn(x, y);
    return *(uint32_t*)&h2;
}

// ---------------------------------------------------------------------------
// bf16x3 HMMA GEMM (unchanged from R6):
//   out[M,N] = A[M,K] * W[N,K]^T + bias[N]  (+ optional GELU)
// ---------------------------------------------------------------------------
#define GST 80                 // row stride bytes
#define SA_H 0
#define SA_L 10240
#define SB_H 20480
#define SB_L 30720
#define GEMM_SMEM_BYTES 40960

__device__ __forceinline__ void hgemm_cta(
    const float* __restrict__ A, const float* __restrict__ W,
    const float* __restrict__ bias, float* __restrict__ out,
    int N, int K, int m0, int n0, bool do_gelu, char* sm)
{
    const uint32_t smb = smem_u32(sm);
    const int tid  = threadIdx.x;
    const int lane = tid & 31;
    const int wid  = tid >> 5;
    const int wm   = wid & 3;
    const int wn   = wid >> 2;

    const int lrow  = tid >> 1;
    const int cbase = (tid & 1) * 16;

    const float* gA = A + (size_t)(m0 + lrow) * K + cbase;
    const float* gB = W + (size_t)(n0 + lrow) * K + cbase;
    const uint32_t srowA = (uint32_t)lrow * GST + (uint32_t)cbase * 2;

    const int lro = (lane & 7) + ((lane >> 3) & 1) * 8;
    const int lck = (lane >> 4) * 16;
    const uint32_t aAddr = smb + (uint32_t)(wm * 32 + lro) * GST + lck;
    const uint32_t bAddr = smb + SB_H + (uint32_t)(wn * 64 + lro) * GST + lck;

    float acc[2][8][4];
#pragma unroll
    for (int i = 0; i < 2; i++)
#pragma unroll
        for (int j = 0; j < 8; j++)
#pragma unroll
            for (int c = 0; c < 4; c++) acc[i][j][c] = 0.0f;

    const int KT = K >> 5;
    for (int kt = 0; kt < KT; ++kt) {
#pragma unroll
        for (int i = 0; i < 4; ++i) {
            float4 a = *(const float4*)(gA + kt * 32 + i * 4);
            uint32_t h0, l0, h1, l1;
            split2(a.x, a.y, h0, l0);
            split2(a.z, a.w, h1, l1);
            uint32_t off = srowA + i * 8;
            *(uint2*)(sm + SA_H + off) = make_uint2(h0, h1);
            *(uint2*)(sm + SA_L + off) = make_uint2(l0, l1);

            float4 b = *(const float4*)(gB + kt * 32 + i * 4);
            split2(b.x, b.y, h0, l0);
            split2(b.z, b.w, h1, l1);
            *(uint2*)(sm + SB_H + off) = make_uint2(h0, h1);
            *(uint2*)(sm + SB_L + off) = make_uint2(l0, l1);
        }
        __syncthreads();

#pragma unroll
        for (int ks = 0; ks < 2; ++ks) {
            const uint32_t kb = ks * 32;
            uint32_t ah[2][4], al[2][4];
#pragma unroll
            for (int mi = 0; mi < 2; ++mi) {
                ldm_x4(ah[mi], aAddr + SA_H + mi * (16 * GST) + kb);
                ldm_x4(al[mi], aAddr + SA_L + mi * (16 * GST) + kb);
            }
#pragma unroll
            for (int ng = 0; ng < 4; ++ng) {
                uint32_t bh[4], bl[4];
                ldm_x4(bh, bAddr + ng * (16 * GST) + kb);
                ldm_x4(bl, bAddr + (SB_L - SB_H) + ng * (16 * GST) + kb);
#pragma unroll
                for (int mi = 0; mi < 2; ++mi) {
#pragma unroll
                    for (int hf = 0; hf < 2; ++hf) {
                        float* d = acc[mi][ng * 2 + hf];
                        mma_bf16(d, ah[mi], bh[hf], bh[2 + hf]);
                        mma_bf16(d, al[mi], bh[hf], bh[2 + hf]);
                        mma_bf16(d, ah[mi], bl[hf], bl[2 + hf]);
                    }
                }
            }
        }
        __syncthreads();
    }

    const int r0 = m0 + wm * 32 + (lane >> 2);
    const int c0 = n0 + wn * 64 + (lane & 3) * 2;
#pragma unroll
    for (int mi = 0; mi < 2; ++mi) {
#pragma unroll
        for (int nf = 0; nf < 8; ++nf) {
            int col = c0 + nf * 8;
            float b0 = bias[col], b1 = bias[col + 1];
#pragma unroll
            for (int half = 0; half < 2; ++half) {
                int row = r0 + mi * 16 + half * 8;
                float v0 = acc[mi][nf][half * 2 + 0] + b0;
                float v1 = acc[mi][nf][half * 2 + 1] + b1;
                if (do_gelu) { v0 = gelu_f(v0); v1 = gelu_f(v1); }
                *(float2*)(out + (size_t)row * N + col) = make_float2(v0, v1);
            }
        }
    }
}

__global__ __launch_bounds__(256)
void hgemm_kernel(const float* __restrict__ A, const float* __restrict__ W,
                  const float* __restrict__ bias, float* __restrict__ out,
                  int N, int K, int do_gelu)
{
    __shared__ char sm[GEMM_SMEM_BYTES];
    hgemm_cta(A, W, bias, out, N, K, blockIdx.y * 128, blockIdx.x * 128,
              do_gelu != 0, sm);
}

__global__ __launch_bounds__(256)
void qkv_hgemm_kernel(const float* __restrict__ A,
                      const float* __restrict__ WQ, const float* __restrict__ bQ, float* __restrict__ Q,
                      const float* __restrict__ WK, const float* __restrict__ bK, float* __restrict__ Kp,
                      const float* __restrict__ WV, const float* __restrict__ bV, float* __restrict__ Vp)
{
    __shared__ char sm[GEMM_SMEM_BYTES];
    const float* W; const float* b; float* o;
    if (blockIdx.z == 0)      { W = WQ; b = bQ; o = Q;  }
    else if (blockIdx.z == 1) { W = WK; b = bK; o = Kp; }
    else                      { W = WV; b = bV; o = Vp; }
    hgemm_cta(A, W, b, o, EE, EE, blockIdx.y * 128, blockIdx.x * 128, false, sm);
}

// ---------------------------------------------------------------------------
// Flash attention with mma.sync (bf16 Q/K/V/P, fp32 accum, online softmax).
// Block = (b, h, 128 q rows). 8 warps x 16 q-rows. KV tiles of 64.
// SMEM tiles [row][64] bf16, row stride 144B (36 words => ldmatrix rows hit
// words 4i mod 32: conflict-free).
// ---------------------------------------------------------------------------
#define QSTR 144

__global__ __launch_bounds__(256, 2)
void attn_mma_kernel(const float* __restrict__ q, const float* __restrict__ k,
                     const float* __restrict__ v, const float* __restrict__ bias,
                     float* __restrict__ out)
{
    __shared__ char sQ[128 * QSTR];
    __shared__ char sK[64 * QSTR];
    __shared__ char sV[64 * QSTR];
    __shared__ float sBias[64];

    const int b   = blockIdx.z;
    const int h   = blockIdx.y;
    const int q0  = blockIdx.x * 128;
    const int tid = threadIdx.x;
    const int lane = tid & 31;
    const int w    = tid >> 5;

    // ---- load Q tile (pre-scaled by 1/sqrt(D)=0.125), fp32 -> bf16 ----
#pragma unroll
    for (int it = 0; it < 8; ++it) {
        int idx = tid + it * 256;          // 0..2047 float4 chunks
        int row = idx >> 4;                // 0..127
        int ch  = idx & 15;
        float4 a = *(const float4*)(q + ((size_t)b * SS + q0 + row) * EE + h * DD + ch * 4);
        uint32_t p0 = pack_bf16(a.x * 0.125f, a.y * 0.125f);
        uint32_t p1 = pack_bf16(a.z * 0.125f, a.w * 0.125f);
        *(uint2*)(sQ + row * QSTR + ch * 8) = make_uint2(p0, p1);
    }
    __syncthreads();

    // ldmatrix lane addressing
    const int lro = (lane & 7) + ((lane >> 3) & 1) * 8;   // row 0..15
    const int kcb = (lane >> 4) * 16;                     // 16B chunk select
    const uint32_t uQ = smem_u32(sQ);
    const uint32_t uK = smem_u32(sK);
    const uint32_t uV = smem_u32(sV);

    // hoist Q fragments: aq[ks][4] covers k = ks*16 .. ks*16+15
    uint32_t aq[4][4];
#pragma unroll
    for (int ks = 0; ks < 4; ++ks)
        ldm_x4(aq[ks], uQ + (uint32_t)(w * 16 + lro) * QSTR + ks * 32 + kcb);

    float o[8][4];
#pragma unroll
    for (int nf = 0; nf < 8; ++nf)
#pragma unroll
        for (int c = 0; c < 4; ++c) o[nf][c] = 0.0f;
    float m0r = -INFINITY, m1r = -INFINITY, l0r = 0.0f, l1r = 0.0f;

    const float* bias_b = bias + b * SS;

    for (int t0 = 0; t0 < SS; t0 += 64) {
        __syncthreads();   // prior tile fully consumed

        // ---- load K, V tiles (fp32 -> bf16), bias slice ----
#pragma unroll
        for (int it = 0; it < 4; ++it) {
            int idx = tid + it * 256;      // 0..1023
            int kvr = idx >> 4;            // 0..63
            int ch  = idx & 15;
            float4 a = *(const float4*)(k + ((size_t)b * SS + t0 + kvr) * EE + h * DD + ch * 4);
            *(uint2*)(sK + kvr * QSTR + ch * 8) =
                make_uint2(pack_bf16(a.x, a.y), pack_bf16(a.z, a.w));
            float4 vv = *(const float4*)(v + ((size_t)b * SS + t0 + kvr) * EE + h * DD + ch * 4);
            *(uint2*)(sV + kvr * QSTR + ch * 8) =
                make_uint2(pack_bf16(vv.x, vv.y), pack_bf16(vv.z, vv.w));
        }
        if (tid < 64) sBias[tid] = bias_b[t0 + tid];
        __syncthreads();

        // ---- S = (Q*0.125) K^T ----
        float s[8][4];
#pragma unroll
        for (int nf = 0; nf < 8; ++nf)
#pragma unroll
            for (int c = 0; c < 4; ++c) s[nf][c] = 0.0f;

#pragma unroll
        for (int ks = 0; ks < 4; ++ks) {
#pragma unroll
            for (int ng = 0; ng < 4; ++ng) {
                uint32_t bk[4];
                ldm_x4(bk, uK + (uint32_t)(ng * 16 + lro) * QSTR + ks * 32 + kcb);
                mma_bf16(s[ng * 2 + 0], aq[ks], bk[0], bk[2]);
                mma_bf16(s[ng * 2 + 1], aq[ks], bk[1], bk[3]);
            }
        }

        // ---- mask bias ----
#pragma unroll
        for (int nf = 0; nf < 8; ++nf) {
            int c = nf * 8 + (lane & 3) * 2;
            float b0 = sBias[c], b1 = sBias[c + 1];
            s[nf][0] -= b0; s[nf][1] -= b1;
            s[nf][2] -= b0; s[nf][3] -= b1;
        }

        // ---- online softmax (rows r0 = lane>>2, r1 = r0+8) ----
        float tm0 = -INFINITY, tm1 = -INFINITY;
#pragma unroll
        for (int nf = 0; nf < 8; ++nf) {
            tm0 = fmaxf(tm0, fmaxf(s[nf][0], s[nf][1]));
            tm1 = fmaxf(tm1, fmaxf(s[nf][2], s[nf][3]));
        }
#pragma unroll
        for (int ox = 1; ox < 4; ox <<= 1) {
            tm0 = fmaxf(tm0, __shfl_xor_sync(0xffffffffu, tm0, ox));
            tm1 = fmaxf(tm1, __shfl_xor_sync(0xffffffffu, tm1, ox));
        }
        float mn0 = fmaxf(m0r, tm0);
        float mn1 = fmaxf(m1r, tm1);
        float al0 = __expf(m0r - mn0);
        float al1 = __expf(m1r - mn1);
        m0r = mn0; m1r = mn1;

        float rs0 = 0.0f, rs1 = 0.0f;
#pragma unroll
        for (int nf = 0; nf < 8; ++nf) {
            s[nf][0] = __expf(s[nf][0] - mn0);
            s[nf][1] = __expf(s[nf][1] - mn0);
            s[nf][2] = __expf(s[nf][2] - mn1);
            s[nf][3] = __expf(s[nf][3] - mn1);
            rs0 += s[nf][0] + s[nf][1];
            rs1 += s[nf][2] + s[nf][3];
        }
#pragma unroll
        for (int ox = 1; ox < 4; ox <<= 1) {
            rs0 += __shfl_xor_sync(0xffffffffu, rs0, ox);
            rs1 += __shfl_xor_sync(0xffffffffu, rs1, ox);
        }
        l0r = l0r * al0 + rs0;
        l1r = l1r * al1 + rs1;

#pragma unroll
        for (int nf = 0; nf < 8; ++nf) {
            o[nf][0] *= al0; o[nf][1] *= al0;
            o[nf][2] *= al1; o[nf][3] *= al1;
        }

        // ---- O += P V  (P from registers; V via ldmatrix.trans) ----
#pragma unroll
        for (int ks = 0; ks < 4; ++ks) {
            uint32_t ap[4];
            ap[0] = pack_bf16(s[2 * ks][0],     s[2 * ks][1]);
            ap[1] = pack_bf16(s[2 * ks][2],     s[2 * ks][3]);
            ap[2] = pack_bf16(s[2 * ks + 1][0], s[2 * ks + 1][1]);
            ap[3] = pack_bf16(s[2 * ks + 1][2], s[2 * ks + 1][3]);
#pragma unroll
            for (int dg = 0; dg < 4; ++dg) {
                uint32_t bv[4];
                ldm_x4_trans(bv, uV + (uint32_t)(ks * 16 + lro) * QSTR + dg * 32 + kcb);
                mma_bf16(o[dg * 2 + 0], ap, bv[0], bv[1]);
                mma_bf16(o[dg * 2 + 1], ap, bv[2], bv[3]);
            }
        }
    }

    // ---- normalize and store ----
    float inv0 = 1.0f / l0r;
    float inv1 = 1.0f / l1r;
    const int r0 = q0 + w * 16 + (lane >> 2);
#pragma unroll
    for (int nf = 0; nf < 8; ++nf) {
        int col = nf * 8 + (lane & 3) * 2;
        *(float2*)(out + ((size_t)b * SS + r0) * EE + h * DD + col) =
            make_float2(o[nf][0] * inv0, o[nf][1] * inv0);
        *(float2*)(out + ((size_t)b * SS + r0 + 8) * EE + h * DD + col) =
            make_float2(o[nf][2] * inv1, o[nf][3] * inv1);
    }
}

// ---------------------------------------------------------------------------
// Residual add + LayerNorm (unchanged)
// ---------------------------------------------------------------------------
__global__ __launch_bounds__(256)
void add_ln_kernel(const float* __restrict__ x, const float* __restrict__ r,
                   const float* __restrict__ g, const float* __restrict__ bt,
                   float* __restrict__ out)
{
    const int row = blockIdx.x;
    const int t = threadIdx.x;
    const size_t base = (size_t)row * EE;

    float v0 = x[base + t]       + r[base + t];
    float v1 = x[base + t + 256] + r[base + t + 256];
    float s  = v0 + v1;
    float ss = v0 * v0 + v1 * v1;
#pragma unroll
    for (int o = 16; o; o >>= 1) {
        s  += __shfl_xor_sync(0xffffffffu, s, o);
        ss += __shfl_xor_sync(0xffffffffu, ss, o);
    }
    __shared__ float sh_s[8], sh_ss[8];
    if ((t & 31) == 0) { sh_s[t >> 5] = s; sh_ss[t >> 5] = ss; }
    __syncthreads();
    float tot = 0.0f, tot2 = 0.0f;
#pragma unroll
    for (int i = 0; i < 8; i++) { tot += sh_s[i]; tot2 += sh_ss[i]; }
    float mean = tot * (1.0f / EE);
    float var  = tot2 * (1.0f / EE) - mean * mean;
    float inv  = rsqrtf(var + 1e-5f);

    out[base + t]       = g[t]       * ((v0 - mean) * inv) + bt[t];
    out[base + t + 256] = g[t + 256] * ((v1 - mean) * inv) + bt[t + 256];
}

// ---------------------------------------------------------------------------
// Host driver
// ---------------------------------------------------------------------------
extern "C" void kernel_launch(void* const* d_in, const int* in_sizes, int n_in,
                              void* d_out, int out_size)
{
    (void)in_sizes; (void)n_in; (void)out_size;

    const float* x_in = (const float*)d_in[0];
    const void*  mask = d_in[1];
    const float* WQ = (const float*)d_in[2];
    const float* bQ = (const float*)d_in[3];
    const float* WK = (const float*)d_in[4];
    const float* bK = (const float*)d_in[5];
    const float* WV = (const float*)d_in[6];
    const float* bV = (const float*)d_in[7];
    const float* WO = (const float*)d_in[8];
    const float* bO = (const float*)d_in[9];
    const float* W1 = (const float*)d_in[10];
    const float* b1 = (const float*)d_in[11];
    const float* W2 = (const float*)d_in[12];
    const float* b2 = (const float*)d_in[13];
    const float* g1 = (const float*)d_in[14];
    const float* t1 = (const float*)d_in[15];
    const float* g2 = (const float*)d_in[16];
    const float* t2 = (const float*)d_in[17];

    float *px, *pq, *pk, *pv, *patt, *ptmp, *ph, *pbias;
    cudaGetSymbolAddress((void**)&px,   g_x);
    cudaGetSymbolAddress((void**)&pq,   g_q);
    cudaGetSymbolAddress((void**)&pk,   g_k);
    cudaGetSymbolAddress((void**)&pv,   g_v);
    cudaGetSymbolAddress((void**)&patt, g_att);
    cudaGetSymbolAddress((void**)&ptmp, g_tmp);
    cudaGetSymbolAddress((void**)&ph,   g_h);
    cudaGetSymbolAddress((void**)&pbias, g_bias);

    cudaMemcpyAsync(px, x_in, sizeof(float) * MM * EE, cudaMemcpyDeviceToDevice);
    detect_mask_kernel<<<1, 256>>>((const unsigned char*)mask);
    mask_bias_kernel<<<(BB * SS + 255) / 256, 256>>>(mask, pbias);

    for (int l = 0; l < LL; l++) {
        const float* wq = WQ + (size_t)l * EE * EE;
        const float* wk = WK + (size_t)l * EE * EE;
        const float* wv = WV + (size_t)l * EE * EE;
        const float* wo = WO + (size_t)l * EE * EE;
        const float* w1 = W1 + (size_t)l * HFF * EE;
        const float* w2 = W2 + (size_t)l * EE * HFF;

        qkv_hgemm_kernel<<<dim3(EE / 128, MM / 128, 3), 256>>>(
            px, wq, bQ + l * EE, pq, wk, bK + l * EE, pk, wv, bV + l * EE, pv);

        attn_mma_kernel<<<dim3(SS / 128, HH, BB), 256>>>(pq, pk, pv, pbias, patt);

        hgemm_kernel<<<dim3(EE / 128, MM / 128), 256>>>(
            patt, wo, bO + l * EE, ptmp, EE, EE, 0);

        add_ln_kernel<<<MM, 256>>>(px, ptmp, g1 + l * EE, t1 + l * EE, px);

        hgemm_kernel<<<dim3(HFF / 128, MM / 128), 256>>>(
            px, w1, b1 + l * HFF, ph, HFF, EE, 1);

        hgemm_kernel<<<dim3(EE / 128, MM / 128), 256>>>(
            ph, w2, b2 + l * EE, ptmp, EE, HFF, 0);

        float* xout = (l == LL - 1) ? (float*)d_out : px;
        add_ln_kernel<<<MM, 256>>>(px, ptmp, g2 + l * EE, t2 + l * EE, xout);
    }
}